// round 15
// baseline (speedup 1.0000x reference)
#include <cuda_runtime.h>
#include <cuda_fp16.h>
#include <cstdint>
#include <math.h>

#define HIDDEN 256
#define SEQ    233
#define BATCH  1024
#define MROWS  (BATCH * SEQ)          // 238592 = 128 * 1864
#define SCALE  0.0625f                // 1/sqrt(256)
#define NEG    (-10000.0f)

// Scratch buffers
static __device__ __half  g_Xhi[(size_t)MROWS * 256];   // x fp16
static __device__ __half  g_Z  [(size_t)MROWS * 256];   // z = x·M fp16
static __device__ __half  g_Y  [(size_t)MROWS * 256];   // y = probs·x fp16
static __device__ __half  g_Wz [256 * 256];             // Wz[o][k] = M[k][o]
static __device__ __half  g_Wc [256 * 512];             // [W0 | -W3] k-major
static __device__ float   g_w  [MROWS];                 // x_j·(W2^T b1)  (col term)
static __device__ float   g_v2 [256];

__device__ __forceinline__ uint32_t smem_u32(const void* p) {
    uint32_t a;
    asm("{ .reg .u64 t; cvta.to.shared.u64 t, %1; cvt.u32.u64 %0, t; }" : "=r"(a) : "l"(p));
    return a;
}
__device__ __forceinline__ uint32_t h2u(__half2 h) {
    return *reinterpret_cast<uint32_t*>(&h);
}
__device__ __forceinline__ void ldmatrix_x4(uint32_t* r, uint32_t addr) {
    asm volatile("ldmatrix.sync.aligned.m8n8.x4.shared.b16 {%0,%1,%2,%3}, [%4];"
                 : "=r"(r[0]), "=r"(r[1]), "=r"(r[2]), "=r"(r[3]) : "r"(addr));
}
__device__ __forceinline__ void ldmatrix_x4_t(uint32_t* r, uint32_t addr) {
    asm volatile("ldmatrix.sync.aligned.m8n8.x4.trans.shared.b16 {%0,%1,%2,%3}, [%4];"
                 : "=r"(r[0]), "=r"(r[1]), "=r"(r[2]), "=r"(r[3]) : "r"(addr));
}
__device__ __forceinline__ void mma_f16(float* c, const uint32_t* a, const uint32_t* b) {
    asm volatile(
        "mma.sync.aligned.m16n8k16.row.col.f32.f16.f16.f32 "
        "{%0,%1,%2,%3}, {%4,%5,%6,%7}, {%8,%9}, {%0,%1,%2,%3};"
        : "+f"(c[0]), "+f"(c[1]), "+f"(c[2]), "+f"(c[3])
        : "r"(a[0]), "r"(a[1]), "r"(a[2]), "r"(a[3]), "r"(b[0]), "r"(b[1]));
}

#define CP_A16(dst, src) asm volatile("cp.async.cg.shared.global [%0], [%1], 16;" :: "r"(dst), "l"(src))
#define CP_COMMIT()      asm volatile("cp.async.commit_group;")
#define CP_WAIT(n)       asm volatile("cp.async.wait_group %0;" :: "n"(n))

// ===========================================================================
// Prep kernels (tiny, once)
// ===========================================================================
// v2[k] = sum_t W2[t][k]*b1[t]   (the only surviving rank-1 score term)
__global__ void __launch_bounds__(256) prep_v_kernel(
    const float* __restrict__ W2, const float* __restrict__ b1)
{
    const int k = threadIdx.x;
    float a2 = 0.f;
    for (int t = 0; t < 256; ++t)
        a2 += W2[t * 256 + k] * b1[t];
    g_v2[k] = a2;
}
// Wz[o][k] = M[k][o] = sum_t W1[t][k]*W2[t][o]
__global__ void __launch_bounds__(256) prep_M_kernel(
    const float* __restrict__ W1, const float* __restrict__ W2)
{
    const int o = blockIdx.x;
    const int k = threadIdx.x;
    float a = 0.f;
    for (int t = 0; t < 256; ++t)
        a += W1[t * 256 + k] * W2[t * 256 + o];
    g_Wz[o * 256 + k] = __float2half_rn(a);
}
// Wc[o][0..255] = W0[o][:], Wc[o][256..511] = -W3[o][:]
__global__ void __launch_bounds__(256) prep_wc_kernel(
    const float* __restrict__ W0, const float* __restrict__ W3)
{
    const int o = blockIdx.x;
    const int k = threadIdx.x;
    g_Wc[o * 512 + k]       = __float2half_rn(W0[o * 256 + k]);
    g_Wc[o * 512 + 256 + k] = __float2half_rn(-W3[o * 256 + k]);
}

// ===========================================================================
// X converter: fp32 -> fp16, plus w = x.v2 (warp per row, v2 staged in SMEM)
// ===========================================================================
__global__ void __launch_bounds__(256) cvt_x_kernel(
    const float* __restrict__ src, size_t n8)
{
    __shared__ float sv2[256];
    sv2[threadIdx.x] = g_v2[threadIdx.x];
    __syncthreads();

    const size_t i = (size_t)blockIdx.x * blockDim.x + threadIdx.x;
    if (i >= n8) return;
    const int lane = threadIdx.x & 31;
    const float4 v0 = __ldg((const float4*)(src + i * 8));
    const float4 v1 = __ldg((const float4*)(src + i * 8 + 4));
    uint4 h;
    h.x = h2u(__floats2half2_rn(v0.x, v0.y));
    h.y = h2u(__floats2half2_rn(v0.z, v0.w));
    h.z = h2u(__floats2half2_rn(v1.x, v1.y));
    h.w = h2u(__floats2half2_rn(v1.z, v1.w));
    *(uint4*)(g_Xhi + i * 8) = h;

    const int co = lane * 8;
    const float4 a0 = *(const float4*)&sv2[co];
    const float4 a1 = *(const float4*)&sv2[co + 4];
    float dw = v0.x * a0.x + v0.y * a0.y + v0.z * a0.z + v0.w * a0.w
             + v1.x * a1.x + v1.y * a1.y + v1.z * a1.z + v1.w * a1.w;
#pragma unroll
    for (int o = 16; o; o >>= 1)
        dw += __shfl_xor_sync(0xffffffffu, dw, o);
    if (lane == 0) g_w[i >> 5] = dw;
}

// ===========================================================================
// Kernel A: z = x · Wz^T (single-pass fp16), grid (2, 1864). cp.async 3-stage.
// Stage (32KB): A 16K | B 16K.
// ===========================================================================
#define PJ_STAGE 32768
#define PJ_SMEM  (3 * PJ_STAGE)

__global__ void __launch_bounds__(256, 1) projz_mma_kernel()
{
    extern __shared__ __align__(16) char smp[];
    const uint32_t sbase = smem_u32(smp);

    const int tid  = threadIdx.x;
    const int wid  = tid >> 5;
    const int lane = tid & 31;
    const int wm   = wid & 3;
    const int wn   = wid >> 2;

    const int bx = blockIdx.x;         // 0,1 : 128-col slab of z
    const int m0 = blockIdx.y * 128;

    float acc[2][8][4];
#pragma unroll
    for (int i = 0; i < 2; ++i)
#pragma unroll
        for (int j = 0; j < 8; ++j)
#pragma unroll
            for (int q = 0; q < 4; ++q) acc[i][j][q] = 0.0f;

    const int a_row = lane & 15;
    const int a_gh  = lane >> 4;
    const int b_nof = (lane & 7) + ((lane & 16) ? 8 : 0);
    const int b_gh  = (lane >> 3) & 1;

    auto issue = [&](int c, int buf) {
        const uint32_t sb = sbase + buf * PJ_STAGE;
#pragma unroll
        for (int it = 0; it < 4; ++it) {
            const int gi  = tid + it * 256;
            const int row = gi >> 3;
            const int g   = gi & 7;
            const uint32_t o = row * 128 + ((g ^ (row & 7)) << 4);
            CP_A16(sb + o,         (const char*)(g_Xhi + (size_t)(m0 + row) * 256 + c * 64 + g * 8));
            CP_A16(sb + 16384 + o, (const char*)(g_Wz  + (size_t)(bx * 128 + row) * 256 + c * 64 + g * 8));
        }
        CP_COMMIT();
    };

    auto compute = [&](int buf) {
        const uint32_t sA = sbase + buf * PJ_STAGE;
        const uint32_t sB = sA + 16384;
#pragma unroll
        for (int ks = 0; ks < 4; ++ks) {
            uint32_t ah[2][4];
#pragma unroll
            for (int im = 0; im < 2; ++im) {
                const int row = wm * 32 + im * 16 + a_row;
                const int g   = ks * 2 + a_gh;
                ldmatrix_x4(ah[im], sA + row * 128 + ((g ^ (row & 7)) << 4));
            }
            uint32_t bh[4][4];
#pragma unroll
            for (int bp = 0; bp < 4; ++bp) {
                const int row = wn * 64 + bp * 16 + b_nof;
                const int g   = ks * 2 + b_gh;
                ldmatrix_x4(bh[bp], sB + row * 128 + ((g ^ (row & 7)) << 4));
            }
#pragma unroll
            for (int im = 0; im < 2; ++im)
#pragma unroll
                for (int in = 0; in < 8; ++in)
                    mma_f16(acc[im][in], ah[im], &bh[in >> 1][(in & 1) * 2]);
        }
    };

    issue(0, 0);
    issue(1, 1);
    issue(2, 2);
    CP_WAIT(2); __syncthreads();
    compute(0);
    __syncthreads();
    issue(3, 0);
    CP_WAIT(2); __syncthreads();
    compute(1);
    CP_WAIT(1); __syncthreads();
    compute(2);
    CP_WAIT(0); __syncthreads();
    compute(0);

    const int r  = lane >> 2;
    const int cc = (lane & 3) * 2;
#pragma unroll
    for (int im = 0; im < 2; ++im) {
        const int mr = m0 + wm * 32 + im * 16 + r;
#pragma unroll
        for (int in = 0; in < 8; ++in) {
            const int ncol = bx * 128 + wn * 64 + in * 8 + cc;
            *(uint32_t*)&g_Z[(size_t)mr * 256 + ncol] =
                h2u(__floats2half2_rn(acc[im][in][0], acc[im][in][1]));
            *(uint32_t*)&g_Z[(size_t)(mr + 8) * 256 + ncol] =
                h2u(__floats2half2_rn(acc[im][in][2], acc[im][in][3]));
        }
    }
}

// ===========================================================================
// Kernel B: attention -> y = probs·x. Segment-packed (2 CTAs/batch).
//   scores = (z·x^T + w_j)·SCALE with masks (row-constant term dropped:
//   softmax-invariant); y stored fp16.
// SMEM: ph1 Q(z)[0,32K) K(x)[32K,64K); sscore [120][129] aliases [0,62K);
//   V(x) [0,64K) ph3; sP @64K; sw @96K. -> 2 CTAs/SM.
// ===========================================================================
#define AT_SP   65536
#define AT_UW   98304
#define AT_SMEM 99328

__global__ void __launch_bounds__(256, 2) attn_mma_kernel()
{
    extern __shared__ __align__(16) char smp[];
    const uint32_t sQhi = smem_u32(smp);
    const uint32_t sKhi = sQhi + 32768;
    const uint32_t sVhi = sQhi;            // phase3 alias [128 j][256 h] fp16
    float* sscore = (float*)smp;           // [120][129] fp32 aliases Q/K
    const uint32_t sP = sQhi + AT_SP;
    float* sw = (float*)(smp + AT_UW);     // [128]

    const int seg = blockIdx.x;            // 0: law+term packed, 1: accu
    const int b   = blockIdx.y;
    const int n   = seg ? 119 : 114;
    const size_t base = (size_t)b * SEQ;

    const int tid  = threadIdx.x;
    const int wid  = tid >> 5;
    const int lane = tid & 31;
    const int wm   = wid & 3;
    const int wn   = wid >> 2;

    const int a_row = lane & 15;
    const int a_gh  = lane >> 4;
    const int b_nof = (lane & 7) + ((lane & 16) ? 8 : 0);
    const int b_gh  = (lane >> 3) & 1;

    auto tok = [&](int r) -> int {
        return seg ? (103 + r) : (r < 103 ? r : r + 119);
    };

    if (tid < 128) {
        const bool v = tid < n;
        const int  t = v ? tok(tid) : 0;
        sw[tid] = v ? g_w[base + t] : 0.f;
    }

    float acc[2][8][4];
#pragma unroll
    for (int i = 0; i < 2; ++i)
#pragma unroll
        for (int j = 0; j < 8; ++j)
#pragma unroll
            for (int q = 0; q < 4; ++q) acc[i][j][q] = 0.0f;

    // ============ phase 1: z · x^T, 2 K-chunks
#pragma unroll 1
    for (int kc = 0; kc < 2; ++kc) {
        if (kc) __syncthreads();
#pragma unroll
        for (int it = 0; it < 8; ++it) {
            const int gi = tid + it * 256;
            const int row = gi >> 4, g = gi & 15;
            uint4 vh = make_uint4(0,0,0,0);
            if (row < n)
                vh = *(const uint4*)&g_Z[(base + tok(row)) * 256 + kc * 128 + g * 8];
            *(uint4*)(smp + row * 256 + ((g ^ (row & 7)) << 4)) = vh;
        }
#pragma unroll
        for (int it = 0; it < 8; ++it) {
            const int gi = tid + it * 256;
            const int row = gi >> 4, g = gi & 15;
            uint4 vh = make_uint4(0,0,0,0);
            if (row < n)
                vh = *(const uint4*)&g_Xhi[(base + tok(row)) * 256 + kc * 128 + g * 8];
            *(uint4*)(smp + 32768 + row * 256 + ((g ^ (row & 7)) << 4)) = vh;
        }
        __syncthreads();

#pragma unroll
        for (int ks = 0; ks < 8; ++ks) {
            uint32_t ah[2][4];
#pragma unroll
            for (int im = 0; im < 2; ++im) {
                const int row = wm * 32 + im * 16 + a_row;
                const int g   = ks * 2 + a_gh;
                ldmatrix_x4(ah[im], sQhi + row * 256 + ((g ^ (row & 7)) << 4));
            }
            uint32_t bh[4][4];
#pragma unroll
            for (int bp = 0; bp < 4; ++bp) {
                const int row = wn * 64 + bp * 16 + b_nof;
                const int g   = ks * 2 + b_gh;
                ldmatrix_x4(bh[bp], sKhi + row * 256 + ((g ^ (row & 7)) << 4));
            }
#pragma unroll
            for (int im = 0; im < 2; ++im)
#pragma unroll
                for (int in = 0; in < 8; ++in)
                    mma_f16(acc[im][in], ah[im], &bh[in >> 1][(in & 1) * 2]);
        }
        __syncthreads();
    }

    // ============ phase 2: (acc + w_j)·SCALE + masks -> sscore
    {
        const int r  = lane >> 2;
        const int cc = (lane & 3) * 2;
#pragma unroll
        for (int im = 0; im < 2; ++im) {
            const int g1 = wm * 32 + im * 16 + r;
            const int g2 = g1 + 8;
#pragma unroll
            for (int in = 0; in < 8; ++in) {
                const int col = wn * 64 + in * 8 + cc;
                const bool cb0 = (col < 103), cb1 = (col + 1 < 103);
                const float w0 = sw[col], w1 = sw[col + 1];
                if (g1 < n) {
                    const bool rB = (g1 < 103);
                    const bool m0 = (col     >= n) || (col     == g1) || (seg == 0 && (rB != cb0));
                    const bool m1 = (col + 1 >= n) || (col + 1 == g1) || (seg == 0 && (rB != cb1));
                    sscore[g1 * 129 + col]     = m0 ? NEG : (acc[im][in][0] + w0) * SCALE;
                    sscore[g1 * 129 + col + 1] = m1 ? NEG : (acc[im][in][1] + w1) * SCALE;
                }
                if (g2 < n) {
                    const bool rB = (g2 < 103);
                    const bool m0 = (col     >= n) || (col     == g2) || (seg == 0 && (rB != cb0));
                    const bool m1 = (col + 1 >= n) || (col + 1 == g2) || (seg == 0 && (rB != cb1));
                    sscore[g2 * 129 + col]     = m0 ? NEG : (acc[im][in][2] + w0) * SCALE;
                    sscore[g2 * 129 + col + 1] = m1 ? NEG : (acc[im][in][3] + w1) * SCALE;
                }
            }
        }
    }
    __syncthreads();

    // ============ softmax: 8 warps x 15 rows, 128 cols
#pragma unroll 1
    for (int rr = 0; rr < 15; ++rr) {
        const int gi = rr * 8 + wid;
        if (gi < n) {
            float* rowp = &sscore[gi * 129];
            float mx = -1e30f;
#pragma unroll
            for (int j = 0; j < 4; ++j) mx = fmaxf(mx, rowp[lane + j * 32]);
#pragma unroll
            for (int o = 16; o; o >>= 1) mx = fmaxf(mx, __shfl_xor_sync(0xffffffffu, mx, o));
            float ssum = 0.f;
            float ev[4];
#pragma unroll
            for (int j = 0; j < 4; ++j) {
                ev[j] = __expf(rowp[lane + j * 32] - mx);
                ssum += ev[j];
            }
#pragma unroll
            for (int o = 16; o; o >>= 1) ssum += __shfl_xor_sync(0xffffffffu, ssum, o);
            const float inv = 1.0f / ssum;
#pragma unroll
            for (int j = 0; j < 4; ++j) rowp[lane + j * 32] = ev[j] * inv;
        }
    }
    __syncthreads();

    // ============ convert probs -> sP fp16 (before V overwrites sscore)
#pragma unroll
    for (int it = 0; it < 8; ++it) {
        const int gi = tid + it * 256;
        const int row = gi >> 4, g = gi & 15;
        uint4 v = make_uint4(0, 0, 0, 0);
        if (row < n) {
            const float* rp = &sscore[row * 129 + g * 8];
            v.x = h2u(__floats2half2_rn(rp[0], rp[1]));
            v.y = h2u(__floats2half2_rn(rp[2], rp[3]));
            v.z = h2u(__floats2half2_rn(rp[4], rp[5]));
            v.w = h2u(__floats2half2_rn(rp[6], rp[7]));
        }
        *(uint4*)(smp + AT_SP + row * 256 + ((g ^ (row & 7)) << 4)) = v;
    }
    __syncthreads();

    // ============ load V = x over the dead sscore region
#pragma unroll
    for (int it = 0; it < 16; ++it) {
        const int gi = tid + it * 256;
        const int j = gi >> 5, gg = gi & 31;
        uint4 vh = make_uint4(0,0,0,0);
        if (j < n) vh = *(const uint4*)&g_Xhi[(base + tok(j)) * 256 + gg * 8];
        *(uint4*)(smp + j * 512 + ((gg ^ (j & 7)) << 4)) = vh;
    }
    __syncthreads();

    // ============ phase 3: y = probs @ x, two 128-col halves -> g_Y fp16
#pragma unroll 1
    for (int hb = 0; hb < 2; ++hb) {
        float acc2[2][8][4];
#pragma unroll
        for (int i = 0; i < 2; ++i)
#pragma unroll
            for (int j = 0; j < 8; ++j)
#pragma unroll
                for (int q = 0; q < 4; ++q) acc2[i][j][q] = 0.0f;

#pragma unroll
        for (int ks = 0; ks < 8; ++ks) {
            uint32_t ap[2][4];
#pragma unroll
            for (int im = 0; im < 2; ++im) {
                const int row = wm * 32 + im * 16 + a_row;
                const int g   = ks * 2 + a_gh;
                ldmatrix_x4(ap[im], sP + row * 256 + ((g ^ (row & 7)) << 4));
            }
            uint32_t bvh[4][4];
#pragma unroll
            for (int bp = 0; bp < 4; ++bp) {
                const int jrow = ks * 16 + (lane & 15);
                const int gg   = hb * 16 + wn * 8 + bp * 2 + (lane >> 4);
                ldmatrix_x4_t(bvh[bp], sVhi + jrow * 512 + ((gg ^ (jrow & 7)) << 4));
            }
#pragma unroll
            for (int im = 0; im < 2; ++im)
#pragma unroll
                for (int in = 0; in < 8; ++in)
                    mma_f16(acc2[im][in], ap[im], &bvh[in >> 1][(in & 1) * 2]);
        }

        const int r  = lane >> 2;
        const int cc = (lane & 3) * 2;
#pragma unroll
        for (int im = 0; im < 2; ++im) {
            const int g1 = wm * 32 + im * 16 + r;
#pragma unroll
            for (int in = 0; in < 8; ++in) {
                const int h = hb * 128 + wn * 64 + in * 8 + cc;
                if (g1 < n) {
                    const size_t grow = base + tok(g1);
                    *(uint32_t*)&g_Y[grow * 256 + h] =
                        h2u(__floats2half2_rn(acc2[im][in][0], acc2[im][in][1]));
                }
                const int g2 = g1 + 8;
                if (g2 < n) {
                    const size_t grow = base + tok(g2);
                    *(uint32_t*)&g_Y[grow * 256 + h] =
                        h2u(__floats2half2_rn(acc2[im][in][2], acc2[im][in][3]));
                }
            }
        }
    }
}

// ===========================================================================
// Kernel C: out = [x | y] · [W0 | -W3]^T + (b0 - b3). K=512 (8 chunks of 64).
// cp.async 3-stage, grid (2, 1864).
// ===========================================================================
__global__ void __launch_bounds__(256, 1) final_mma_kernel(
    const float* __restrict__ B0, const float* __restrict__ B3,
    float* __restrict__ out)
{
    extern __shared__ __align__(16) char smp[];
    const uint32_t sbase = smem_u32(smp);

    const int tid  = threadIdx.x;
    const int wid  = tid >> 5;
    const int lane = tid & 31;
    const int wm   = wid & 3;
    const int wn   = wid >> 2;

    const int bx = blockIdx.x;         // 0,1 : 128-col slab of the output
    const int m0 = blockIdx.y * 128;

    float acc[2][8][4];
#pragma unroll
    for (int i = 0; i < 2; ++i)
#pragma unroll
        for (int j = 0; j < 8; ++j)
#pragma unroll
            for (int q = 0; q < 4; ++q) acc[i][j][q] = 0.0f;

    const int a_row = lane & 15;
    const int a_gh  = lane >> 4;
    const int b_nof = (lane & 7) + ((lane & 16) ? 8 : 0);
    const int b_gh  = (lane >> 3) & 1;

    auto issue = [&](int c, int buf) {
        const uint32_t sb = sbase + buf * PJ_STAGE;
        const __half* asrc = (c < 4) ? g_Xhi : g_Y;
        const int ck = (c & 3) * 64;
#pragma unroll
        for (int it = 0; it < 4; ++it) {
            const int gi  = tid + it * 256;
            const int row = gi >> 3;
            const int g   = gi & 7;
            const uint32_t o = row * 128 + ((g ^ (row & 7)) << 4);
            CP_A16(sb + o,         (const char*)(asrc + (size_t)(m0 + row) * 256 + ck + g * 8));
            CP_A16(sb + 16384 + o, (const char*)(g_Wc + (size_t)(bx * 128 + row) * 512 + c * 64 + g * 8));
        }
        CP_COMMIT();
    };

    auto compute = [&](int buf) {
        const uint32_t sA = sbase + buf * PJ_STAGE;
        const uint32_t sB = sA + 16384;
#pragma unroll
        for (int ks = 0; ks < 4; ++ks) {
            uint32_t ah[2][4];
#pragma unroll
            for (int im = 0; im < 2; ++im) {
                const int row = wm * 32 + im * 16 + a_row;
                const int g   = ks * 2 + a_gh;
                ldmatrix_x4(ah[im], sA + row * 128 + ((g ^ (row & 7)) << 4));
            }
            uint32_t bh[4][4];
#pragma unroll
            for (int bp = 0; bp < 4; ++bp) {
                const int row = wn * 64 + bp * 16 + b_nof;
                const int g   = ks * 2 + b_gh;
                ldmatrix_x4(bh[bp], sB + row * 128 + ((g ^ (row & 7)) << 4));
            }
#pragma unroll
            for (int im = 0; im < 2; ++im)
#pragma unroll
                for (int in = 0; in < 8; ++in)
                    mma_f16(acc[im][in], ah[im], &bh[in >> 1][(in & 1) * 2]);
        }
    };

    issue(0, 0);
    issue(1, 1);
    issue(2, 2);
    CP_WAIT(2); __syncthreads(); compute(0); __syncthreads(); issue(3, 0);
    CP_WAIT(2); __syncthreads(); compute(1); __syncthreads(); issue(4, 1);
    CP_WAIT(2); __syncthreads(); compute(2); __syncthreads(); issue(5, 2);
    CP_WAIT(2); __syncthreads(); compute(0); __syncthreads(); issue(6, 0);
    CP_WAIT(2); __syncthreads(); compute(1); __syncthreads(); issue(7, 1);
    CP_WAIT(2); __syncthreads(); compute(2);
    CP_WAIT(1); __syncthreads(); compute(0);
    CP_WAIT(0); __syncthreads(); compute(1);

    const int r  = lane >> 2;
    const int cc = (lane & 3) * 2;
#pragma unroll
    for (int im = 0; im < 2; ++im) {
        const int mr = m0 + wm * 32 + im * 16 + r;
#pragma unroll
        for (int in = 0; in < 8; ++in) {
            const int ncol = wn * 64 + in * 8 + cc;
            const int col  = bx * 128 + ncol;
            const float2 b0v = __ldg((const float2*)(B0 + col));
            const float2 b3v = __ldg((const float2*)(B3 + col));
            const float bxv = b0v.x - b3v.x, byv = b0v.y - b3v.y;
            *(float2*)&out[(size_t)mr * 256 + col] =
                make_float2(acc[im][in][0] + bxv, acc[im][in][1] + byv);
            *(float2*)&out[(size_t)(mr + 8) * 256 + col] =
                make_float2(acc[im][in][2] + bxv, acc[im][in][3] + byv);
        }
    }
}

// ---------------------------------------------------------------------------
extern "C" void kernel_launch(void* const* d_in, const int* in_sizes, int n_in,
                              void* d_out, int out_size)
{
    const float* toks = (const float*)d_in[0];
    const float* W0   = (const float*)d_in[1];
    const float* b0   = (const float*)d_in[2];
    const float* W1   = (const float*)d_in[3];
    const float* b1   = (const float*)d_in[4];
    const float* W2   = (const float*)d_in[5];
    // b2 unused: its score contribution is row-constant -> softmax-invariant
    const float* W3   = (const float*)d_in[7];
    const float* b3   = (const float*)d_in[8];
    float* out = (float*)d_out;

    // Prep (tiny)
    prep_v_kernel<<<1, 256>>>(W2, b1);
    prep_M_kernel<<<256, 256>>>(W1, W2);
    prep_wc_kernel<<<256, 256>>>(W0, W3);

    // X convert + w scalars
    const size_t x8 = (size_t)MROWS * 256 / 8;
    cvt_x_kernel<<<(unsigned)((x8 + 255) / 256), 256>>>(toks, x8);

    // z = x · M
    cudaFuncSetAttribute(projz_mma_kernel,
                         cudaFuncAttributeMaxDynamicSharedMemorySize, PJ_SMEM);
    dim3 gZ(2, MROWS / 128);
    projz_mma_kernel<<<gZ, 256, PJ_SMEM>>>();

    // attention -> y
    cudaFuncSetAttribute(attn_mma_kernel,
                         cudaFuncAttributeMaxDynamicSharedMemorySize, AT_SMEM);
    dim3 gB(2, BATCH);
    attn_mma_kernel<<<gB, 256, AT_SMEM>>>();

    // out = [x|y]·[W0|-W3]^T + (b0-b3)
    cudaFuncSetAttribute(final_mma_kernel,
                         cudaFuncAttributeMaxDynamicSharedMemorySize, PJ_SMEM);
    dim3 gF(2, MROWS / 128);
    final_mma_kernel<<<gF, 256, PJ_SMEM>>>(b0, b3, out);
}

// round 16
// speedup vs baseline: 1.0033x; 1.0033x over previous
#include <cuda_runtime.h>
#include <cuda_fp16.h>
#include <cstdint>
#include <math.h>

#define HIDDEN 256
#define SEQ    233
#define BATCH  1024
#define MROWS  (BATCH * SEQ)          // 238592 = 128 * 1864
#define SCALE  0.0625f                // 1/sqrt(256)
#define NEG    (-10000.0f)

// Scratch buffers
static __device__ __half  g_Xhi[(size_t)MROWS * 256];   // x fp16
static __device__ __half  g_Z  [(size_t)MROWS * 256];   // z = x·M fp16
static __device__ __half  g_Y  [(size_t)MROWS * 256];   // y = probs·x fp16
static __device__ __half  g_Wz [256 * 256];             // Wz[o][k] = M[k][o]
static __device__ __half  g_Wc [256 * 512];             // [W0 | -W3] k-major
static __device__ float   g_w  [MROWS];                 // x_j·(W2^T b1)  (col term)
static __device__ float   g_v2 [256];

__device__ __forceinline__ uint32_t smem_u32(const void* p) {
    uint32_t a;
    asm("{ .reg .u64 t; cvta.to.shared.u64 t, %1; cvt.u32.u64 %0, t; }" : "=r"(a) : "l"(p));
    return a;
}
__device__ __forceinline__ uint32_t h2u(__half2 h) {
    return *reinterpret_cast<uint32_t*>(&h);
}
__device__ __forceinline__ void ldmatrix_x4(uint32_t* r, uint32_t addr) {
    asm volatile("ldmatrix.sync.aligned.m8n8.x4.shared.b16 {%0,%1,%2,%3}, [%4];"
                 : "=r"(r[0]), "=r"(r[1]), "=r"(r[2]), "=r"(r[3]) : "r"(addr));
}
__device__ __forceinline__ void ldmatrix_x4_t(uint32_t* r, uint32_t addr) {
    asm volatile("ldmatrix.sync.aligned.m8n8.x4.trans.shared.b16 {%0,%1,%2,%3}, [%4];"
                 : "=r"(r[0]), "=r"(r[1]), "=r"(r[2]), "=r"(r[3]) : "r"(addr));
}
__device__ __forceinline__ void mma_f16(float* c, const uint32_t* a, const uint32_t* b) {
    asm volatile(
        "mma.sync.aligned.m16n8k16.row.col.f32.f16.f16.f32 "
        "{%0,%1,%2,%3}, {%4,%5,%6,%7}, {%8,%9}, {%0,%1,%2,%3};"
        : "+f"(c[0]), "+f"(c[1]), "+f"(c[2]), "+f"(c[3])
        : "r"(a[0]), "r"(a[1]), "r"(a[2]), "r"(a[3]), "r"(b[0]), "r"(b[1]));
}

#define CP_A16(dst, src) asm volatile("cp.async.cg.shared.global [%0], [%1], 16;" :: "r"(dst), "l"(src))
#define CP_COMMIT()      asm volatile("cp.async.commit_group;")
#define CP_WAIT(n)       asm volatile("cp.async.wait_group %0;" :: "n"(n))

// ===========================================================================
// Prep kernels (tiny, once)
// ===========================================================================
// v2[k] = sum_t W2[t][k]*b1[t]   (the only surviving rank-1 score term)
__global__ void __launch_bounds__(256) prep_v_kernel(
    const float* __restrict__ W2, const float* __restrict__ b1)
{
    const int k = threadIdx.x;
    float a2 = 0.f;
    for (int t = 0; t < 256; ++t)
        a2 += W2[t * 256 + k] * b1[t];
    g_v2[k] = a2;
}
// Wz[o][k] = M[k][o] = sum_t W1[t][k]*W2[t][o]
__global__ void __launch_bounds__(256) prep_M_kernel(
    const float* __restrict__ W1, const float* __restrict__ W2)
{
    const int o = blockIdx.x;
    const int k = threadIdx.x;
    float a = 0.f;
    for (int t = 0; t < 256; ++t)
        a += W1[t * 256 + k] * W2[t * 256 + o];
    g_Wz[o * 256 + k] = __float2half_rn(a);
}
// Wc[o][0..255] = W0[o][:], Wc[o][256..511] = -W3[o][:]
__global__ void __launch_bounds__(256) prep_wc_kernel(
    const float* __restrict__ W0, const float* __restrict__ W3)
{
    const int o = blockIdx.x;
    const int k = threadIdx.x;
    g_Wc[o * 512 + k]       = __float2half_rn(W0[o * 256 + k]);
    g_Wc[o * 512 + 256 + k] = __float2half_rn(-W3[o * 256 + k]);
}

// ===========================================================================
// X converter: fp32 -> fp16, plus w = x.v2 (warp per row, v2 staged in SMEM)
// ===========================================================================
__global__ void __launch_bounds__(256) cvt_x_kernel(
    const float* __restrict__ src, size_t n8)
{
    __shared__ float sv2[256];
    sv2[threadIdx.x] = g_v2[threadIdx.x];
    __syncthreads();

    const size_t i = (size_t)blockIdx.x * blockDim.x + threadIdx.x;
    if (i >= n8) return;
    const int lane = threadIdx.x & 31;
    const float4 v0 = __ldg((const float4*)(src + i * 8));
    const float4 v1 = __ldg((const float4*)(src + i * 8 + 4));
    uint4 h;
    h.x = h2u(__floats2half2_rn(v0.x, v0.y));
    h.y = h2u(__floats2half2_rn(v0.z, v0.w));
    h.z = h2u(__floats2half2_rn(v1.x, v1.y));
    h.w = h2u(__floats2half2_rn(v1.z, v1.w));
    *(uint4*)(g_Xhi + i * 8) = h;

    const int co = lane * 8;
    const float4 a0 = *(const float4*)&sv2[co];
    const float4 a1 = *(const float4*)&sv2[co + 4];
    float dw = v0.x * a0.x + v0.y * a0.y + v0.z * a0.z + v0.w * a0.w
             + v1.x * a1.x + v1.y * a1.y + v1.z * a1.z + v1.w * a1.w;
#pragma unroll
    for (int o = 16; o; o >>= 1)
        dw += __shfl_xor_sync(0xffffffffu, dw, o);
    if (lane == 0) g_w[i >> 5] = dw;
}

// ===========================================================================
// Kernel A: z = x · Wz^T (single-pass fp16), grid (2, 1864). cp.async 3-stage.
// Stage (32KB): A 16K | B 16K.
// ===========================================================================
#define PJ_STAGE 32768
#define PJ_SMEM  (3 * PJ_STAGE)

__global__ void __launch_bounds__(256, 1) projz_mma_kernel()
{
    extern __shared__ __align__(16) char smp[];
    const uint32_t sbase = smem_u32(smp);

    const int tid  = threadIdx.x;
    const int wid  = tid >> 5;
    const int lane = tid & 31;
    const int wm   = wid & 3;
    const int wn   = wid >> 2;

    const int bx = blockIdx.x;         // 0,1 : 128-col slab of z
    const int m0 = blockIdx.y * 128;

    float acc[2][8][4];
#pragma unroll
    for (int i = 0; i < 2; ++i)
#pragma unroll
        for (int j = 0; j < 8; ++j)
#pragma unroll
            for (int q = 0; q < 4; ++q) acc[i][j][q] = 0.0f;

    const int a_row = lane & 15;
    const int a_gh  = lane >> 4;
    const int b_nof = (lane & 7) + ((lane & 16) ? 8 : 0);
    const int b_gh  = (lane >> 3) & 1;

    auto issue = [&](int c, int buf) {
        const uint32_t sb = sbase + buf * PJ_STAGE;
#pragma unroll
        for (int it = 0; it < 4; ++it) {
            const int gi  = tid + it * 256;
            const int row = gi >> 3;
            const int g   = gi & 7;
            const uint32_t o = row * 128 + ((g ^ (row & 7)) << 4);
            CP_A16(sb + o,         (const char*)(g_Xhi + (size_t)(m0 + row) * 256 + c * 64 + g * 8));
            CP_A16(sb + 16384 + o, (const char*)(g_Wz  + (size_t)(bx * 128 + row) * 256 + c * 64 + g * 8));
        }
        CP_COMMIT();
    };

    auto compute = [&](int buf) {
        const uint32_t sA = sbase + buf * PJ_STAGE;
        const uint32_t sB = sA + 16384;
#pragma unroll
        for (int ks = 0; ks < 4; ++ks) {
            uint32_t ah[2][4];
#pragma unroll
            for (int im = 0; im < 2; ++im) {
                const int row = wm * 32 + im * 16 + a_row;
                const int g   = ks * 2 + a_gh;
                ldmatrix_x4(ah[im], sA + row * 128 + ((g ^ (row & 7)) << 4));
            }
            uint32_t bh[4][4];
#pragma unroll
            for (int bp = 0; bp < 4; ++bp) {
                const int row = wn * 64 + bp * 16 + b_nof;
                const int g   = ks * 2 + b_gh;
                ldmatrix_x4(bh[bp], sB + row * 128 + ((g ^ (row & 7)) << 4));
            }
#pragma unroll
            for (int im = 0; im < 2; ++im)
#pragma unroll
                for (int in = 0; in < 8; ++in)
                    mma_f16(acc[im][in], ah[im], &bh[in >> 1][(in & 1) * 2]);
        }
    };

    issue(0, 0);
    issue(1, 1);
    issue(2, 2);
    CP_WAIT(2); __syncthreads();
    compute(0);
    __syncthreads();
    issue(3, 0);
    CP_WAIT(2); __syncthreads();
    compute(1);
    CP_WAIT(1); __syncthreads();
    compute(2);
    CP_WAIT(0); __syncthreads();
    compute(0);

    const int r  = lane >> 2;
    const int cc = (lane & 3) * 2;
#pragma unroll
    for (int im = 0; im < 2; ++im) {
        const int mr = m0 + wm * 32 + im * 16 + r;
#pragma unroll
        for (int in = 0; in < 8; ++in) {
            const int ncol = bx * 128 + wn * 64 + in * 8 + cc;
            *(uint32_t*)&g_Z[(size_t)mr * 256 + ncol] =
                h2u(__floats2half2_rn(acc[im][in][0], acc[im][in][1]));
            *(uint32_t*)&g_Z[(size_t)(mr + 8) * 256 + ncol] =
                h2u(__floats2half2_rn(acc[im][in][2], acc[im][in][3]));
        }
    }
}

// ===========================================================================
// Kernel B: attention -> y = probs·x. Segment-packed (2 CTAs/batch).
//   scores = (z·x^T + w_j)·SCALE with masks (row-constant term dropped:
//   softmax-invariant); y stored fp16.
// SMEM: ph1 Q(z)[0,32K) K(x)[32K,64K); sscore [120][129] aliases [0,62K);
//   V(x) [0,64K) ph3; sP @64K; sw @96K. -> 2 CTAs/SM.
// ===========================================================================
#define AT_SP   65536
#define AT_UW   98304
#define AT_SMEM 99328

__global__ void __launch_bounds__(256, 2) attn_mma_kernel()
{
    extern __shared__ __align__(16) char smp[];
    const uint32_t sQhi = smem_u32(smp);
    const uint32_t sKhi = sQhi + 32768;
    const uint32_t sVhi = sQhi;            // phase3 alias [128 j][256 h] fp16
    float* sscore = (float*)smp;           // [120][129] fp32 aliases Q/K
    const uint32_t sP = sQhi + AT_SP;
    float* sw = (float*)(smp + AT_UW);     // [128]

    const int seg = blockIdx.x;            // 0: law+term packed, 1: accu
    const int b   = blockIdx.y;
    const int n   = seg ? 119 : 114;
    const size_t base = (size_t)b * SEQ;

    const int tid  = threadIdx.x;
    const int wid  = tid >> 5;
    const int lane = tid & 31;
    const int wm   = wid & 3;
    const int wn   = wid >> 2;

    const int a_row = lane & 15;
    const int a_gh  = lane >> 4;
    const int b_nof = (lane & 7) + ((lane & 16) ? 8 : 0);
    const int b_gh  = (lane >> 3) & 1;

    auto tok = [&](int r) -> int {
        return seg ? (103 + r) : (r < 103 ? r : r + 119);
    };

    if (tid < 128) {
        const bool v = tid < n;
        const int  t = v ? tok(tid) : 0;
        sw[tid] = v ? g_w[base + t] : 0.f;
    }

    float acc[2][8][4];
#pragma unroll
    for (int i = 0; i < 2; ++i)
#pragma unroll
        for (int j = 0; j < 8; ++j)
#pragma unroll
            for (int q = 0; q < 4; ++q) acc[i][j][q] = 0.0f;

    // ============ phase 1: z · x^T, 2 K-chunks
#pragma unroll 1
    for (int kc = 0; kc < 2; ++kc) {
        if (kc) __syncthreads();
#pragma unroll
        for (int it = 0; it < 8; ++it) {
            const int gi = tid + it * 256;
            const int row = gi >> 4, g = gi & 15;
            uint4 vh = make_uint4(0,0,0,0);
            if (row < n)
                vh = *(const uint4*)&g_Z[(base + tok(row)) * 256 + kc * 128 + g * 8];
            *(uint4*)(smp + row * 256 + ((g ^ (row & 7)) << 4)) = vh;
        }
#pragma unroll
        for (int it = 0; it < 8; ++it) {
            const int gi = tid + it * 256;
            const int row = gi >> 4, g = gi & 15;
            uint4 vh = make_uint4(0,0,0,0);
            if (row < n)
                vh = *(const uint4*)&g_Xhi[(base + tok(row)) * 256 + kc * 128 + g * 8];
            *(uint4*)(smp + 32768 + row * 256 + ((g ^ (row & 7)) << 4)) = vh;
        }
        __syncthreads();

#pragma unroll
        for (int ks = 0; ks < 8; ++ks) {
            uint32_t ah[2][4];
#pragma unroll
            for (int im = 0; im < 2; ++im) {
                const int row = wm * 32 + im * 16 + a_row;
                const int g   = ks * 2 + a_gh;
                ldmatrix_x4(ah[im], sQhi + row * 256 + ((g ^ (row & 7)) << 4));
            }
            uint32_t bh[4][4];
#pragma unroll
            for (int bp = 0; bp < 4; ++bp) {
                const int row = wn * 64 + bp * 16 + b_nof;
                const int g   = ks * 2 + b_gh;
                ldmatrix_x4(bh[bp], sKhi + row * 256 + ((g ^ (row & 7)) << 4));
            }
#pragma unroll
            for (int im = 0; im < 2; ++im)
#pragma unroll
                for (int in = 0; in < 8; ++in)
                    mma_f16(acc[im][in], ah[im], &bh[in >> 1][(in & 1) * 2]);
        }
        __syncthreads();
    }

    // ============ phase 2: (acc + w_j)·SCALE + masks -> sscore
    {
        const int r  = lane >> 2;
        const int cc = (lane & 3) * 2;
#pragma unroll
        for (int im = 0; im < 2; ++im) {
            const int g1 = wm * 32 + im * 16 + r;
            const int g2 = g1 + 8;
#pragma unroll
            for (int in = 0; in < 8; ++in) {
                const int col = wn * 64 + in * 8 + cc;
                const bool cb0 = (col < 103), cb1 = (col + 1 < 103);
                const float w0 = sw[col], w1 = sw[col + 1];
                if (g1 < n) {
                    const bool rB = (g1 < 103);
                    const bool m0 = (col     >= n) || (col     == g1) || (seg == 0 && (rB != cb0));
                    const bool m1 = (col + 1 >= n) || (col + 1 == g1) || (seg == 0 && (rB != cb1));
                    sscore[g1 * 129 + col]     = m0 ? NEG : (acc[im][in][0] + w0) * SCALE;
                    sscore[g1 * 129 + col + 1] = m1 ? NEG : (acc[im][in][1] + w1) * SCALE;
                }
                if (g2 < n) {
                    const bool rB = (g2 < 103);
                    const bool m0 = (col     >= n) || (col     == g2) || (seg == 0 && (rB != cb0));
                    const bool m1 = (col + 1 >= n) || (col + 1 == g2) || (seg == 0 && (rB != cb1));
                    sscore[g2 * 129 + col]     = m0 ? NEG : (acc[im][in][2] + w0) * SCALE;
                    sscore[g2 * 129 + col + 1] = m1 ? NEG : (acc[im][in][3] + w1) * SCALE;
                }
            }
        }
    }
    __syncthreads();

    // ============ softmax: 8 warps x 15 rows, 128 cols
#pragma unroll 1
    for (int rr = 0; rr < 15; ++rr) {
        const int gi = rr * 8 + wid;
        if (gi < n) {
            float* rowp = &sscore[gi * 129];
            float mx = -1e30f;
#pragma unroll
            for (int j = 0; j < 4; ++j) mx = fmaxf(mx, rowp[lane + j * 32]);
#pragma unroll
            for (int o = 16; o; o >>= 1) mx = fmaxf(mx, __shfl_xor_sync(0xffffffffu, mx, o));
            float ssum = 0.f;
            float ev[4];
#pragma unroll
            for (int j = 0; j < 4; ++j) {
                ev[j] = __expf(rowp[lane + j * 32] - mx);
                ssum += ev[j];
            }
#pragma unroll
            for (int o = 16; o; o >>= 1) ssum += __shfl_xor_sync(0xffffffffu, ssum, o);
            const float inv = 1.0f / ssum;
#pragma unroll
            for (int j = 0; j < 4; ++j) rowp[lane + j * 32] = ev[j] * inv;
        }
    }
    __syncthreads();

    // ============ convert probs -> sP fp16 (before V overwrites sscore)
#pragma unroll
    for (int it = 0; it < 8; ++it) {
        const int gi = tid + it * 256;
        const int row = gi >> 4, g = gi & 15;
        uint4 v = make_uint4(0, 0, 0, 0);
        if (row < n) {
            const float* rp = &sscore[row * 129 + g * 8];
            v.x = h2u(__floats2half2_rn(rp[0], rp[1]));
            v.y = h2u(__floats2half2_rn(rp[2], rp[3]));
            v.z = h2u(__floats2half2_rn(rp[4], rp[5]));
            v.w = h2u(__floats2half2_rn(rp[6], rp[7]));
        }
        *(uint4*)(smp + AT_SP + row * 256 + ((g ^ (row & 7)) << 4)) = v;
    }
    __syncthreads();

    // ============ load V = x over the dead sscore region
#pragma unroll
    for (int it = 0; it < 16; ++it) {
        const int gi = tid + it * 256;
        const int j = gi >> 5, gg = gi & 31;
        uint4 vh = make_uint4(0,0,0,0);
        if (j < n) vh = *(const uint4*)&g_Xhi[(base + tok(j)) * 256 + gg * 8];
        *(uint4*)(smp + j * 512 + ((gg ^ (j & 7)) << 4)) = vh;
    }
    __syncthreads();

    // ============ phase 3: y = probs @ x, two 128-col halves -> g_Y fp16
#pragma unroll 1
    for (int hb = 0; hb < 2; ++hb) {
        float acc2[2][8][4];
#pragma unroll
        for (int i = 0; i < 2; ++i)
#pragma unroll
            for (int j = 0; j < 8; ++j)
#pragma unroll
                for (int q = 0; q < 4; ++q) acc2[i][j][q] = 0.0f;

#pragma unroll
        for (int ks = 0; ks < 8; ++ks) {
            uint32_t ap[2][4];
#pragma unroll
            for (int im = 0; im < 2; ++im) {
                const int row = wm * 32 + im * 16 + a_row;
                const int g   = ks * 2 + a_gh;
                ldmatrix_x4(ap[im], sP + row * 256 + ((g ^ (row & 7)) << 4));
            }
            uint32_t bvh[4][4];
#pragma unroll
            for (int bp = 0; bp < 4; ++bp) {
                const int jrow = ks * 16 + (lane & 15);
                const int gg   = hb * 16 + wn * 8 + bp * 2 + (lane >> 4);
                ldmatrix_x4_t(bvh[bp], sVhi + jrow * 512 + ((gg ^ (jrow & 7)) << 4));
            }
#pragma unroll
            for (int im = 0; im < 2; ++im)
#pragma unroll
                for (int in = 0; in < 8; ++in)
                    mma_f16(acc2[im][in], ap[im], &bvh[in >> 1][(in & 1) * 2]);
        }

        const int r  = lane >> 2;
        const int cc = (lane & 3) * 2;
#pragma unroll
        for (int im = 0; im < 2; ++im) {
            const int g1 = wm * 32 + im * 16 + r;
#pragma unroll
            for (int in = 0; in < 8; ++in) {
                const int h = hb * 128 + wn * 64 + in * 8 + cc;
                if (g1 < n) {
                    const size_t grow = base + tok(g1);
                    *(uint32_t*)&g_Y[grow * 256 + h] =
                        h2u(__floats2half2_rn(acc2[im][in][0], acc2[im][in][1]));
                }
                const int g2 = g1 + 8;
                if (g2 < n) {
                    const size_t grow = base + tok(g2);
                    *(uint32_t*)&g_Y[grow * 256 + h] =
                        h2u(__floats2half2_rn(acc2[im][in][2], acc2[im][in][3]));
                }
            }
        }
    }
}

// ===========================================================================
// Kernel C: out = [x | y] · [W0 | -W3]^T + (b0 - b3). K=512 (8 chunks of 64).
// cp.async 3-stage, grid (2, 1864).
// ===========================================================================
__global__ void __launch_bounds__(256, 1) final_mma_kernel(
    const float* __restrict__ B0, const float* __restrict__ B3,
    float* __restrict__ out)
{
    extern __shared__ __align__(16) char smp[];
    const uint32_t sbase = smem_u32(smp);

    const int tid  = threadIdx.x;
    const int wid  = tid >> 5;
    const int lane = tid & 31;
    const int wm   = wid & 3;
    const int wn   = wid >> 2;

    const int bx = blockIdx.x;         // 0,1 : 128-col slab of the output
    const int m0 = blockIdx.y * 128;

    float acc[2][8][4];
#pragma unroll
    for (int i = 0; i < 2; ++i)
#pragma unroll
        for (int j = 0; j < 8; ++j)
#pragma unroll
            for (int q = 0; q < 4; ++q) acc[i][j][q] = 0.0f;

    const int a_row = lane & 15;
    const int a_gh  = lane >> 4;
    const int b_nof = (lane & 7) + ((lane & 16) ? 8 : 0);
    const int b_gh  = (lane >> 3) & 1;

    auto issue = [&](int c, int buf) {
        const uint32_t sb = sbase + buf * PJ_STAGE;
        const __half* asrc = (c < 4) ? g_Xhi : g_Y;
        const int ck = (c & 3) * 64;
#pragma unroll
        for (int it = 0; it < 4; ++it) {
            const int gi  = tid + it * 256;
            const int row = gi >> 3;
            const int g   = gi & 7;
            const uint32_t o = row * 128 + ((g ^ (row & 7)) << 4);
            CP_A16(sb + o,         (const char*)(asrc + (size_t)(m0 + row) * 256 + ck + g * 8));
            CP_A16(sb + 16384 + o, (const char*)(g_Wc + (size_t)(bx * 128 + row) * 512 + c * 64 + g * 8));
        }
        CP_COMMIT();
    };

    auto compute = [&](int buf) {
        const uint32_t sA = sbase + buf * PJ_STAGE;
        const uint32_t sB = sA + 16384;
#pragma unroll
        for (int ks = 0; ks < 4; ++ks) {
            uint32_t ah[2][4];
#pragma unroll
            for (int im = 0; im < 2; ++im) {
                const int row = wm * 32 + im * 16 + a_row;
                const int g   = ks * 2 + a_gh;
                ldmatrix_x4(ah[im], sA + row * 128 + ((g ^ (row & 7)) << 4));
            }
            uint32_t bh[4][4];
#pragma unroll
            for (int bp = 0; bp < 4; ++bp) {
                const int row = wn * 64 + bp * 16 + b_nof;
                const int g   = ks * 2 + b_gh;
                ldmatrix_x4(bh[bp], sB + row * 128 + ((g ^ (row & 7)) << 4));
            }
#pragma unroll
            for (int im = 0; im < 2; ++im)
#pragma unroll
                for (int in = 0; in < 8; ++in)
                    mma_f16(acc[im][in], ah[im], &bh[in >> 1][(in & 1) * 2]);
        }
    };

    issue(0, 0);
    issue(1, 1);
    issue(2, 2);
    CP_WAIT(2); __syncthreads(); compute(0); __syncthreads(); issue(3, 0);
    CP_WAIT(2); __syncthreads(); compute(1); __syncthreads(); issue(4, 1);
    CP_WAIT(2); __syncthreads(); compute(2); __syncthreads(); issue(5, 2);
    CP_WAIT(2); __syncthreads(); compute(0); __syncthreads(); issue(6, 0);
    CP_WAIT(2); __syncthreads(); compute(1); __syncthreads(); issue(7, 1);
    CP_WAIT(2); __syncthreads(); compute(2);
    CP_WAIT(1); __syncthreads(); compute(0);
    CP_WAIT(0); __syncthreads(); compute(1);

    const int r  = lane >> 2;
    const int cc = (lane & 3) * 2;
#pragma unroll
    for (int im = 0; im < 2; ++im) {
        const int mr = m0 + wm * 32 + im * 16 + r;
#pragma unroll
        for (int in = 0; in < 8; ++in) {
            const int ncol = wn * 64 + in * 8 + cc;
            const int col  = bx * 128 + ncol;
            const float2 b0v = __ldg((const float2*)(B0 + col));
            const float2 b3v = __ldg((const float2*)(B3 + col));
            const float bxv = b0v.x - b3v.x, byv = b0v.y - b3v.y;
            *(float2*)&out[(size_t)mr * 256 + col] =
                make_float2(acc[im][in][0] + bxv, acc[im][in][1] + byv);
            *(float2*)&out[(size_t)(mr + 8) * 256 + col] =
                make_float2(acc[im][in][2] + bxv, acc[im][in][3] + byv);
        }
    }
}

// ---------------------------------------------------------------------------
extern "C" void kernel_launch(void* const* d_in, const int* in_sizes, int n_in,
                              void* d_out, int out_size)
{
    const float* toks = (const float*)d_in[0];
    const float* W0   = (const float*)d_in[1];
    const float* b0   = (const float*)d_in[2];
    const float* W1   = (const float*)d_in[3];
    const float* b1   = (const float*)d_in[4];
    const float* W2   = (const float*)d_in[5];
    // b2 unused: its score contribution is row-constant -> softmax-invariant
    const float* W3   = (const float*)d_in[7];
    const float* b3   = (const float*)d_in[8];
    float* out = (float*)d_out;

    // Prep (tiny)
    prep_v_kernel<<<1, 256>>>(W2, b1);
    prep_M_kernel<<<256, 256>>>(W1, W2);
    prep_wc_kernel<<<256, 256>>>(W0, W3);

    // X convert + w scalars
    const size_t x8 = (size_t)MROWS * 256 / 8;
    cvt_x_kernel<<<(unsigned)((x8 + 255) / 256), 256>>>(toks, x8);

    // z = x · M
    cudaFuncSetAttribute(projz_mma_kernel,
                         cudaFuncAttributeMaxDynamicSharedMemorySize, PJ_SMEM);
    dim3 gZ(2, MROWS / 128);
    projz_mma_kernel<<<gZ, 256, PJ_SMEM>>>();

    // attention -> y
    cudaFuncSetAttribute(attn_mma_kernel,
                         cudaFuncAttributeMaxDynamicSharedMemorySize, AT_SMEM);
    dim3 gB(2, BATCH);
    attn_mma_kernel<<<gB, 256, AT_SMEM>>>();

    // out = [x|y]·[W0|-W3]^T + (b0-b3)
    cudaFuncSetAttribute(final_mma_kernel,
                         cudaFuncAttributeMaxDynamicSharedMemorySize, PJ_SMEM);
    dim3 gF(2, MROWS / 128);
    final_mma_kernel<<<gF, 256, PJ_SMEM>>>(b0, b3, out);
}

// round 17
// speedup vs baseline: 1.1052x; 1.1015x over previous
#include <cuda_runtime.h>
#include <cuda_fp16.h>
#include <cstdint>
#include <math.h>

#define HIDDEN 256
#define SEQ    233
#define BATCH  1024
#define MROWS  (BATCH * SEQ)          // 238592 = 128 * 1864
#define SCALE  0.0625f                // 1/sqrt(256)
#define NEG    (-10000.0f)

// Scratch buffers
static __device__ __half  g_Xhi[(size_t)MROWS * 256];   // x fp16
static __device__ __half  g_Z  [(size_t)MROWS * 256];   // z = x·M fp16
static __device__ __half  g_Y  [(size_t)MROWS * 256];   // y = probs·x fp16
static __device__ __half  g_Wz [256 * 256];             // Wz[o][k] = M[k][o]
static __device__ __half  g_Wc [256 * 512];             // [W0 | -W3] k-major
static __device__ float   g_w  [MROWS];                 // x_j·(W2^T b1)  (col term)
static __device__ float   g_v2 [256];

__device__ __forceinline__ uint32_t smem_u32(const void* p) {
    uint32_t a;
    asm("{ .reg .u64 t; cvta.to.shared.u64 t, %1; cvt.u32.u64 %0, t; }" : "=r"(a) : "l"(p));
    return a;
}
__device__ __forceinline__ uint32_t h2u(__half2 h) {
    return *reinterpret_cast<uint32_t*>(&h);
}
__device__ __forceinline__ void ldmatrix_x4(uint32_t* r, uint32_t addr) {
    asm volatile("ldmatrix.sync.aligned.m8n8.x4.shared.b16 {%0,%1,%2,%3}, [%4];"
                 : "=r"(r[0]), "=r"(r[1]), "=r"(r[2]), "=r"(r[3]) : "r"(addr));
}
__device__ __forceinline__ void ldmatrix_x4_t(uint32_t* r, uint32_t addr) {
    asm volatile("ldmatrix.sync.aligned.m8n8.x4.trans.shared.b16 {%0,%1,%2,%3}, [%4];"
                 : "=r"(r[0]), "=r"(r[1]), "=r"(r[2]), "=r"(r[3]) : "r"(addr));
}
__device__ __forceinline__ void mma_f16(float* c, const uint32_t* a, const uint32_t* b) {
    asm volatile(
        "mma.sync.aligned.m16n8k16.row.col.f32.f16.f16.f32 "
        "{%0,%1,%2,%3}, {%4,%5,%6,%7}, {%8,%9}, {%0,%1,%2,%3};"
        : "+f"(c[0]), "+f"(c[1]), "+f"(c[2]), "+f"(c[3])
        : "r"(a[0]), "r"(a[1]), "r"(a[2]), "r"(a[3]), "r"(b[0]), "r"(b[1]));
}

#define CP_A16(dst, src) asm volatile("cp.async.cg.shared.global [%0], [%1], 16;" :: "r"(dst), "l"(src))
#define CP_COMMIT()      asm volatile("cp.async.commit_group;")
#define CP_WAIT(n)       asm volatile("cp.async.wait_group %0;" :: "n"(n))

// ===========================================================================
// Prep kernels (tiny, once)
// ===========================================================================
// v2[k] = sum_t W2[t][k]*b1[t]   (the only surviving rank-1 score term)
__global__ void __launch_bounds__(256) prep_v_kernel(
    const float* __restrict__ W2, const float* __restrict__ b1)
{
    const int k = threadIdx.x;
    float a2 = 0.f;
    for (int t = 0; t < 256; ++t)
        a2 += W2[t * 256 + k] * b1[t];
    g_v2[k] = a2;
}
// Wz[o][k] = M[k][o] = sum_t W1[t][k]*W2[t][o]
__global__ void __launch_bounds__(256) prep_M_kernel(
    const float* __restrict__ W1, const float* __restrict__ W2)
{
    const int o = blockIdx.x;
    const int k = threadIdx.x;
    float a = 0.f;
    for (int t = 0; t < 256; ++t)
        a += W1[t * 256 + k] * W2[t * 256 + o];
    g_Wz[o * 256 + k] = __float2half_rn(a);
}
// Wc[o][0..255] = W0[o][:], Wc[o][256..511] = -W3[o][:]
__global__ void __launch_bounds__(256) prep_wc_kernel(
    const float* __restrict__ W0, const float* __restrict__ W3)
{
    const int o = blockIdx.x;
    const int k = threadIdx.x;
    g_Wc[o * 512 + k]       = __float2half_rn(W0[o * 256 + k]);
    g_Wc[o * 512 + 256 + k] = __float2half_rn(-W3[o * 256 + k]);
}

// ===========================================================================
// X converter: fp32 -> fp16, plus w = x.v2 (warp per row, v2 staged in SMEM)
// ===========================================================================
__global__ void __launch_bounds__(256) cvt_x_kernel(
    const float* __restrict__ src, size_t n8)
{
    __shared__ float sv2[256];
    sv2[threadIdx.x] = g_v2[threadIdx.x];
    __syncthreads();

    const size_t i = (size_t)blockIdx.x * blockDim.x + threadIdx.x;
    if (i >= n8) return;
    const int lane = threadIdx.x & 31;
    const float4 v0 = __ldg((const float4*)(src + i * 8));
    const float4 v1 = __ldg((const float4*)(src + i * 8 + 4));
    uint4 h;
    h.x = h2u(__floats2half2_rn(v0.x, v0.y));
    h.y = h2u(__floats2half2_rn(v0.z, v0.w));
    h.z = h2u(__floats2half2_rn(v1.x, v1.y));
    h.w = h2u(__floats2half2_rn(v1.z, v1.w));
    *(uint4*)(g_Xhi + i * 8) = h;

    const int co = lane * 8;
    const float4 a0 = *(const float4*)&sv2[co];
    const float4 a1 = *(const float4*)&sv2[co + 4];
    float dw = v0.x * a0.x + v0.y * a0.y + v0.z * a0.z + v0.w * a0.w
             + v1.x * a1.x + v1.y * a1.y + v1.z * a1.z + v1.w * a1.w;
#pragma unroll
    for (int o = 16; o; o >>= 1)
        dw += __shfl_xor_sync(0xffffffffu, dw, o);
    if (lane == 0) g_w[i >> 5] = dw;
}

// ===========================================================================
// Kernel A: z = x · Wz^T (single-pass fp16), grid (2, 1864). cp.async 3-stage.
// Stage (32KB): A 16K | B 16K.  occ 2 (192KB SMEM/SM, <=128 regs).
// ===========================================================================
#define PJ_STAGE 32768
#define PJ_SMEM  (3 * PJ_STAGE)

__global__ void __launch_bounds__(256, 2) projz_mma_kernel()
{
    extern __shared__ __align__(16) char smp[];
    const uint32_t sbase = smem_u32(smp);

    const int tid  = threadIdx.x;
    const int wid  = tid >> 5;
    const int lane = tid & 31;
    const int wm   = wid & 3;
    const int wn   = wid >> 2;

    const int bx = blockIdx.x;         // 0,1 : 128-col slab of z
    const int m0 = blockIdx.y * 128;

    float acc[2][8][4];
#pragma unroll
    for (int i = 0; i < 2; ++i)
#pragma unroll
        for (int j = 0; j < 8; ++j)
#pragma unroll
            for (int q = 0; q < 4; ++q) acc[i][j][q] = 0.0f;

    const int a_row = lane & 15;
    const int a_gh  = lane >> 4;
    const int b_nof = (lane & 7) + ((lane & 16) ? 8 : 0);
    const int b_gh  = (lane >> 3) & 1;

    auto issue = [&](int c, int buf) {
        const uint32_t sb = sbase + buf * PJ_STAGE;
#pragma unroll
        for (int it = 0; it < 4; ++it) {
            const int gi  = tid + it * 256;
            const int row = gi >> 3;
            const int g   = gi & 7;
            const uint32_t o = row * 128 + ((g ^ (row & 7)) << 4);
            CP_A16(sb + o,         (const char*)(g_Xhi + (size_t)(m0 + row) * 256 + c * 64 + g * 8));
            CP_A16(sb + 16384 + o, (const char*)(g_Wz  + (size_t)(bx * 128 + row) * 256 + c * 64 + g * 8));
        }
        CP_COMMIT();
    };

    auto compute = [&](int buf) {
        const uint32_t sA = sbase + buf * PJ_STAGE;
        const uint32_t sB = sA + 16384;
#pragma unroll
        for (int ks = 0; ks < 4; ++ks) {
            uint32_t ah[2][4];
#pragma unroll
            for (int im = 0; im < 2; ++im) {
                const int row = wm * 32 + im * 16 + a_row;
                const int g   = ks * 2 + a_gh;
                ldmatrix_x4(ah[im], sA + row * 128 + ((g ^ (row & 7)) << 4));
            }
            uint32_t bh[4][4];
#pragma unroll
            for (int bp = 0; bp < 4; ++bp) {
                const int row = wn * 64 + bp * 16 + b_nof;
                const int g   = ks * 2 + b_gh;
                ldmatrix_x4(bh[bp], sB + row * 128 + ((g ^ (row & 7)) << 4));
            }
#pragma unroll
            for (int im = 0; im < 2; ++im)
#pragma unroll
                for (int in = 0; in < 8; ++in)
                    mma_f16(acc[im][in], ah[im], &bh[in >> 1][(in & 1) * 2]);
        }
    };

    issue(0, 0);
    issue(1, 1);
    issue(2, 2);
    CP_WAIT(2); __syncthreads();
    compute(0);
    __syncthreads();
    issue(3, 0);
    CP_WAIT(2); __syncthreads();
    compute(1);
    CP_WAIT(1); __syncthreads();
    compute(2);
    CP_WAIT(0); __syncthreads();
    compute(0);

    const int r  = lane >> 2;
    const int cc = (lane & 3) * 2;
#pragma unroll
    for (int im = 0; im < 2; ++im) {
        const int mr = m0 + wm * 32 + im * 16 + r;
#pragma unroll
        for (int in = 0; in < 8; ++in) {
            const int ncol = bx * 128 + wn * 64 + in * 8 + cc;
            *(uint32_t*)&g_Z[(size_t)mr * 256 + ncol] =
                h2u(__floats2half2_rn(acc[im][in][0], acc[im][in][1]));
            *(uint32_t*)&g_Z[(size_t)(mr + 8) * 256 + ncol] =
                h2u(__floats2half2_rn(acc[im][in][2], acc[im][in][3]));
        }
    }
}

// ===========================================================================
// Kernel B: attention -> y = probs·x. Segment-packed (2 CTAs/batch).
//   scores = (z·x^T + w_j)·SCALE with masks (row-constant term dropped:
//   softmax-invariant); y stored fp16.
// SMEM: ph1 Q(z)[0,32K) K(x)[32K,64K); sscore [120][129] aliases [0,62K);
//   V(x) [0,64K) ph3; sP @64K; sw @96K. -> 2 CTAs/SM.
// ===========================================================================
#define AT_SP   65536
#define AT_UW   98304
#define AT_SMEM 99328

__global__ void __launch_bounds__(256, 2) attn_mma_kernel()
{
    extern __shared__ __align__(16) char smp[];
    const uint32_t sQhi = smem_u32(smp);
    const uint32_t sKhi = sQhi + 32768;
    const uint32_t sVhi = sQhi;            // phase3 alias [128 j][256 h] fp16
    float* sscore = (float*)smp;           // [120][129] fp32 aliases Q/K
    const uint32_t sP = sQhi + AT_SP;
    float* sw = (float*)(smp + AT_UW);     // [128]

    const int seg = blockIdx.x;            // 0: law+term packed, 1: accu
    const int b   = blockIdx.y;
    const int n   = seg ? 119 : 114;
    const size_t base = (size_t)b * SEQ;

    const int tid  = threadIdx.x;
    const int wid  = tid >> 5;
    const int lane = tid & 31;
    const int wm   = wid & 3;
    const int wn   = wid >> 2;

    const int a_row = lane & 15;
    const int a_gh  = lane >> 4;
    const int b_nof = (lane & 7) + ((lane & 16) ? 8 : 0);
    const int b_gh  = (lane >> 3) & 1;

    auto tok = [&](int r) -> int {
        return seg ? (103 + r) : (r < 103 ? r : r + 119);
    };

    if (tid < 128) {
        const bool v = tid < n;
        const int  t = v ? tok(tid) : 0;
        sw[tid] = v ? g_w[base + t] : 0.f;
    }

    float acc[2][8][4];
#pragma unroll
    for (int i = 0; i < 2; ++i)
#pragma unroll
        for (int j = 0; j < 8; ++j)
#pragma unroll
            for (int q = 0; q < 4; ++q) acc[i][j][q] = 0.0f;

    // ============ phase 1: z · x^T, 2 K-chunks
#pragma unroll 1
    for (int kc = 0; kc < 2; ++kc) {
        if (kc) __syncthreads();
#pragma unroll
        for (int it = 0; it < 8; ++it) {
            const int gi = tid + it * 256;
            const int row = gi >> 4, g = gi & 15;
            uint4 vh = make_uint4(0,0,0,0);
            if (row < n)
                vh = *(const uint4*)&g_Z[(base + tok(row)) * 256 + kc * 128 + g * 8];
            *(uint4*)(smp + row * 256 + ((g ^ (row & 7)) << 4)) = vh;
        }
#pragma unroll
        for (int it = 0; it < 8; ++it) {
            const int gi = tid + it * 256;
            const int row = gi >> 4, g = gi & 15;
            uint4 vh = make_uint4(0,0,0,0);
            if (row < n)
                vh = *(const uint4*)&g_Xhi[(base + tok(row)) * 256 + kc * 128 + g * 8];
            *(uint4*)(smp + 32768 + row * 256 + ((g ^ (row & 7)) << 4)) = vh;
        }
        __syncthreads();

#pragma unroll
        for (int ks = 0; ks < 8; ++ks) {
            uint32_t ah[2][4];
#pragma unroll
            for (int im = 0; im < 2; ++im) {
                const int row = wm * 32 + im * 16 + a_row;
                const int g   = ks * 2 + a_gh;
                ldmatrix_x4(ah[im], sQhi + row * 256 + ((g ^ (row & 7)) << 4));
            }
            uint32_t bh[4][4];
#pragma unroll
            for (int bp = 0; bp < 4; ++bp) {
                const int row = wn * 64 + bp * 16 + b_nof;
                const int g   = ks * 2 + b_gh;
                ldmatrix_x4(bh[bp], sKhi + row * 256 + ((g ^ (row & 7)) << 4));
            }
#pragma unroll
            for (int im = 0; im < 2; ++im)
#pragma unroll
                for (int in = 0; in < 8; ++in)
                    mma_f16(acc[im][in], ah[im], &bh[in >> 1][(in & 1) * 2]);
        }
        __syncthreads();
    }

    // ============ phase 2: (acc + w_j)·SCALE + masks -> sscore
    {
        const int r  = lane >> 2;
        const int cc = (lane & 3) * 2;
#pragma unroll
        for (int im = 0; im < 2; ++im) {
            const int g1 = wm * 32 + im * 16 + r;
            const int g2 = g1 + 8;
#pragma unroll
            for (int in = 0; in < 8; ++in) {
                const int col = wn * 64 + in * 8 + cc;
                const bool cb0 = (col < 103), cb1 = (col + 1 < 103);
                const float w0 = sw[col], w1 = sw[col + 1];
                if (g1 < n) {
                    const bool rB = (g1 < 103);
                    const bool m0 = (col     >= n) || (col     == g1) || (seg == 0 && (rB != cb0));
                    const bool m1 = (col + 1 >= n) || (col + 1 == g1) || (seg == 0 && (rB != cb1));
                    sscore[g1 * 129 + col]     = m0 ? NEG : (acc[im][in][0] + w0) * SCALE;
                    sscore[g1 * 129 + col + 1] = m1 ? NEG : (acc[im][in][1] + w1) * SCALE;
                }
                if (g2 < n) {
                    const bool rB = (g2 < 103);
                    const bool m0 = (col     >= n) || (col     == g2) || (seg == 0 && (rB != cb0));
                    const bool m1 = (col + 1 >= n) || (col + 1 == g2) || (seg == 0 && (rB != cb1));
                    sscore[g2 * 129 + col]     = m0 ? NEG : (acc[im][in][2] + w0) * SCALE;
                    sscore[g2 * 129 + col + 1] = m1 ? NEG : (acc[im][in][3] + w1) * SCALE;
                }
            }
        }
    }
    __syncthreads();

    // ============ softmax: 8 warps x 15 rows, 128 cols
#pragma unroll 1
    for (int rr = 0; rr < 15; ++rr) {
        const int gi = rr * 8 + wid;
        if (gi < n) {
            float* rowp = &sscore[gi * 129];
            float mx = -1e30f;
#pragma unroll
            for (int j = 0; j < 4; ++j) mx = fmaxf(mx, rowp[lane + j * 32]);
#pragma unroll
            for (int o = 16; o; o >>= 1) mx = fmaxf(mx, __shfl_xor_sync(0xffffffffu, mx, o));
            float ssum = 0.f;
            float ev[4];
#pragma unroll
            for (int j = 0; j < 4; ++j) {
                ev[j] = __expf(rowp[lane + j * 32] - mx);
                ssum += ev[j];
            }
#pragma unroll
            for (int o = 16; o; o >>= 1) ssum += __shfl_xor_sync(0xffffffffu, ssum, o);
            const float inv = 1.0f / ssum;
#pragma unroll
            for (int j = 0; j < 4; ++j) rowp[lane + j * 32] = ev[j] * inv;
        }
    }
    __syncthreads();

    // ============ convert probs -> sP fp16 (before V overwrites sscore)
#pragma unroll
    for (int it = 0; it < 8; ++it) {
        const int gi = tid + it * 256;
        const int row = gi >> 4, g = gi & 15;
        uint4 v = make_uint4(0, 0, 0, 0);
        if (row < n) {
            const float* rp = &sscore[row * 129 + g * 8];
            v.x = h2u(__floats2half2_rn(rp[0], rp[1]));
            v.y = h2u(__floats2half2_rn(rp[2], rp[3]));
            v.z = h2u(__floats2half2_rn(rp[4], rp[5]));
            v.w = h2u(__floats2half2_rn(rp[6], rp[7]));
        }
        *(uint4*)(smp + AT_SP + row * 256 + ((g ^ (row & 7)) << 4)) = v;
    }
    __syncthreads();

    // ============ load V = x over the dead sscore region
#pragma unroll
    for (int it = 0; it < 16; ++it) {
        const int gi = tid + it * 256;
        const int j = gi >> 5, gg = gi & 31;
        uint4 vh = make_uint4(0,0,0,0);
        if (j < n) vh = *(const uint4*)&g_Xhi[(base + tok(j)) * 256 + gg * 8];
        *(uint4*)(smp + j * 512 + ((gg ^ (j & 7)) << 4)) = vh;
    }
    __syncthreads();

    // ============ phase 3: y = probs @ x, two 128-col halves -> g_Y fp16
#pragma unroll 1
    for (int hb = 0; hb < 2; ++hb) {
        float acc2[2][8][4];
#pragma unroll
        for (int i = 0; i < 2; ++i)
#pragma unroll
            for (int j = 0; j < 8; ++j)
#pragma unroll
                for (int q = 0; q < 4; ++q) acc2[i][j][q] = 0.0f;

#pragma unroll
        for (int ks = 0; ks < 8; ++ks) {
            uint32_t ap[2][4];
#pragma unroll
            for (int im = 0; im < 2; ++im) {
                const int row = wm * 32 + im * 16 + a_row;
                const int g   = ks * 2 + a_gh;
                ldmatrix_x4(ap[im], sP + row * 256 + ((g ^ (row & 7)) << 4));
            }
            uint32_t bvh[4][4];
#pragma unroll
            for (int bp = 0; bp < 4; ++bp) {
                const int jrow = ks * 16 + (lane & 15);
                const int gg   = hb * 16 + wn * 8 + bp * 2 + (lane >> 4);
                ldmatrix_x4_t(bvh[bp], sVhi + jrow * 512 + ((gg ^ (jrow & 7)) << 4));
            }
#pragma unroll
            for (int im = 0; im < 2; ++im)
#pragma unroll
                for (int in = 0; in < 8; ++in)
                    mma_f16(acc2[im][in], ap[im], &bvh[in >> 1][(in & 1) * 2]);
        }

        const int r  = lane >> 2;
        const int cc = (lane & 3) * 2;
#pragma unroll
        for (int im = 0; im < 2; ++im) {
            const int g1 = wm * 32 + im * 16 + r;
#pragma unroll
            for (int in = 0; in < 8; ++in) {
                const int h = hb * 128 + wn * 64 + in * 8 + cc;
                if (g1 < n) {
                    const size_t grow = base + tok(g1);
                    *(uint32_t*)&g_Y[grow * 256 + h] =
                        h2u(__floats2half2_rn(acc2[im][in][0], acc2[im][in][1]));
                }
                const int g2 = g1 + 8;
                if (g2 < n) {
                    const size_t grow = base + tok(g2);
                    *(uint32_t*)&g_Y[grow * 256 + h] =
                        h2u(__floats2half2_rn(acc2[im][in][2], acc2[im][in][3]));
                }
            }
        }
    }
}

// ===========================================================================
// Kernel C: out = [x | y] · [W0 | -W3]^T + (b0 - b3). K=512 (8 chunks of 64).
// cp.async 3-stage, grid (2, 1864). occ 2.
// ===========================================================================
__global__ void __launch_bounds__(256, 2) final_mma_kernel(
    const float* __restrict__ B0, const float* __restrict__ B3,
    float* __restrict__ out)
{
    extern __shared__ __align__(16) char smp[];
    const uint32_t sbase = smem_u32(smp);

    const int tid  = threadIdx.x;
    const int wid  = tid >> 5;
    const int lane = tid & 31;
    const int wm   = wid & 3;
    const int wn   = wid >> 2;

    const int bx = blockIdx.x;         // 0,1 : 128-col slab of the output
    const int m0 = blockIdx.y * 128;

    float acc[2][8][4];
#pragma unroll
    for (int i = 0; i < 2; ++i)
#pragma unroll
        for (int j = 0; j < 8; ++j)
#pragma unroll
            for (int q = 0; q < 4; ++q) acc[i][j][q] = 0.0f;

    const int a_row = lane & 15;
    const int a_gh  = lane >> 4;
    const int b_nof = (lane & 7) + ((lane & 16) ? 8 : 0);
    const int b_gh  = (lane >> 3) & 1;

    auto issue = [&](int c, int buf) {
        const uint32_t sb = sbase + buf * PJ_STAGE;
        const __half* asrc = (c < 4) ? g_Xhi : g_Y;
        const int ck = (c & 3) * 64;
#pragma unroll
        for (int it = 0; it < 4; ++it) {
            const int gi  = tid + it * 256;
            const int row = gi >> 3;
            const int g   = gi & 7;
            const uint32_t o = row * 128 + ((g ^ (row & 7)) << 4);
            CP_A16(sb + o,         (const char*)(asrc + (size_t)(m0 + row) * 256 + ck + g * 8));
            CP_A16(sb + 16384 + o, (const char*)(g_Wc + (size_t)(bx * 128 + row) * 512 + c * 64 + g * 8));
        }
        CP_COMMIT();
    };

    auto compute = [&](int buf) {
        const uint32_t sA = sbase + buf * PJ_STAGE;
        const uint32_t sB = sA + 16384;
#pragma unroll
        for (int ks = 0; ks < 4; ++ks) {
            uint32_t ah[2][4];
#pragma unroll
            for (int im = 0; im < 2; ++im) {
                const int row = wm * 32 + im * 16 + a_row;
                const int g   = ks * 2 + a_gh;
                ldmatrix_x4(ah[im], sA + row * 128 + ((g ^ (row & 7)) << 4));
            }
            uint32_t bh[4][4];
#pragma unroll
            for (int bp = 0; bp < 4; ++bp) {
                const int row = wn * 64 + bp * 16 + b_nof;
                const int g   = ks * 2 + b_gh;
                ldmatrix_x4(bh[bp], sB + row * 128 + ((g ^ (row & 7)) << 4));
            }
#pragma unroll
            for (int im = 0; im < 2; ++im)
#pragma unroll
                for (int in = 0; in < 8; ++in)
                    mma_f16(acc[im][in], ah[im], &bh[in >> 1][(in & 1) * 2]);
        }
    };

    issue(0, 0);
    issue(1, 1);
    issue(2, 2);
    CP_WAIT(2); __syncthreads(); compute(0); __syncthreads(); issue(3, 0);
    CP_WAIT(2); __syncthreads(); compute(1); __syncthreads(); issue(4, 1);
    CP_WAIT(2); __syncthreads(); compute(2); __syncthreads(); issue(5, 2);
    CP_WAIT(2); __syncthreads(); compute(0); __syncthreads(); issue(6, 0);
    CP_WAIT(2); __syncthreads(); compute(1); __syncthreads(); issue(7, 1);
    CP_WAIT(2); __syncthreads(); compute(2);
    CP_WAIT(1); __syncthreads(); compute(0);
    CP_WAIT(0); __syncthreads(); compute(1);

    const int r  = lane >> 2;
    const int cc = (lane & 3) * 2;
#pragma unroll
    for (int im = 0; im < 2; ++im) {
        const int mr = m0 + wm * 32 + im * 16 + r;
#pragma unroll
        for (int in = 0; in < 8; ++in) {
            const int ncol = wn * 64 + in * 8 + cc;
            const int col  = bx * 128 + ncol;
            const float2 b0v = __ldg((const float2*)(B0 + col));
            const float2 b3v = __ldg((const float2*)(B3 + col));
            const float bxv = b0v.x - b3v.x, byv = b0v.y - b3v.y;
            *(float2*)&out[(size_t)mr * 256 + col] =
                make_float2(acc[im][in][0] + bxv, acc[im][in][1] + byv);
            *(float2*)&out[(size_t)(mr + 8) * 256 + col] =
                make_float2(acc[im][in][2] + bxv, acc[im][in][3] + byv);
        }
    }
}

// ---------------------------------------------------------------------------
extern "C" void kernel_launch(void* const* d_in, const int* in_sizes, int n_in,
                              void* d_out, int out_size)
{
    const float* toks = (const float*)d_in[0];
    const float* W0   = (const float*)d_in[1];
    const float* b0   = (const float*)d_in[2];
    const float* W1   = (const float*)d_in[3];
    const float* b1   = (const float*)d_in[4];
    const float* W2   = (const float*)d_in[5];
    // b2 unused: its score contribution is row-constant -> softmax-invariant
    const float* W3   = (const float*)d_in[7];
    const float* b3   = (const float*)d_in[8];
    float* out = (float*)d_out;

    // Prep (tiny)
    prep_v_kernel<<<1, 256>>>(W2, b1);
    prep_M_kernel<<<256, 256>>>(W1, W2);
    prep_wc_kernel<<<256, 256>>>(W0, W3);

    // X convert + w scalars
    const size_t x8 = (size_t)MROWS * 256 / 8;
    cvt_x_kernel<<<(unsigned)((x8 + 255) / 256), 256>>>(toks, x8);

    // z = x · M
    cudaFuncSetAttribute(projz_mma_kernel,
                         cudaFuncAttributeMaxDynamicSharedMemorySize, PJ_SMEM);
    dim3 gZ(2, MROWS / 128);
    projz_mma_kernel<<<gZ, 256, PJ_SMEM>>>();

    // attention -> y
    cudaFuncSetAttribute(attn_mma_kernel,
                         cudaFuncAttributeMaxDynamicSharedMemorySize, AT_SMEM);
    dim3 gB(2, BATCH);
    attn_mma_kernel<<<gB, 256, AT_SMEM>>>();

    // out = [x|y]·[W0|-W3]^T + (b0-b3)
    cudaFuncSetAttribute(final_mma_kernel,
                         cudaFuncAttributeMaxDynamicSharedMemorySize, PJ_SMEM);
    dim3 gF(2, MROWS / 128);
    final_mma_kernel<<<gF, 256, PJ_SMEM>>>(b0, b3, out);
}